// round 9
// baseline (speedup 1.0000x reference)
#include <cuda_runtime.h>
#include <cuda_fp16.h>
#include <cstdint>

#define NSTATES 512
#define MSYMS   256
#define BATCHN  256
#define TLEN    256

#define GB 16                // batch groups (clusters)
#define GI 8                 // i-slices per group = cluster size
#define NB 16                // batch elements per group
#define MI 64                // states per CTA
#define NCTA (GB*GI)         // 128 CTAs
#define NT 256               // 8 warps

#define ESTR 520             // fp16 row stride (1040B), 16B-divisible

// ---- dynamic SMEM layout (bytes) ----
#define BUF_OFF    0                     // float[8][16][18] = 9216
#define STATS_OFF  9216                  // float2 [2][16 b][8 j] = 2048
#define SC_OFF     11264                 // float [16 b][8 j] = 512
#define MB_OFF     11776                 // float[16] = 64
#define P_OFF      11840                 // 64 x 520 fp16 = 66560
#define E_OFF      78400                 // 2 x (16 x 520 fp16) = 33280
#define EBUF_SZ    16640
#define SYMS_OFF   111680                // 16 x 256 int = 16384
#define SMEM_TOTAL 128064

// ---------------- device globals ----------------
__device__ __half gPh[NSTATES * NSTATES];   // column-softmax of transition, fp16
__device__ float  gLET[MSYMS * NSTATES];    // log emission transposed [sym][state]
__device__ float  gLP[NSTATES];             // log priors

// ---------------- PTX helpers ----------------
__device__ __forceinline__ uint32_t smem_u32(const void* p) {
    uint32_t a;
    asm("{ .reg .u64 t; cvta.to.shared.u64 t, %1; cvt.u32.u64 %0, t; }" : "=r"(a) : "l"(p));
    return a;
}
__device__ __forceinline__ uint32_t cluster_rank() {
    uint32_t r; asm("mov.u32 %0, %%cluster_ctarank;" : "=r"(r)); return r;
}
#define CLUSTER_ARRIVE() asm volatile("barrier.cluster.arrive.aligned;" ::: "memory")
#define CLUSTER_WAIT()   asm volatile("barrier.cluster.wait.aligned;"   ::: "memory")

__device__ __forceinline__ void dsmem_st_pair(uint32_t laddr, uint32_t rank, float mx, float sx) {
    asm volatile(
        "{\n\t.reg .b32 r;\n\t"
        "mapa.shared::cluster.u32 r, %0, %1;\n\t"
        "st.shared::cluster.f32 [r], %2;\n\t"
        "st.shared::cluster.f32 [r+4], %3;\n\t}"
        :: "r"(laddr), "r"(rank), "f"(mx), "f"(sx) : "memory");
}
__device__ __forceinline__ void dsmem_st_u64(uint32_t laddr, uint32_t rank, unsigned long long v) {
    asm volatile(
        "{\n\t.reg .b32 r;\n\t"
        "mapa.shared::cluster.u32 r, %0, %1;\n\t"
        "st.shared::cluster.u64 [r], %2;\n\t}"
        :: "r"(laddr), "r"(rank), "l"(v) : "memory");
}
__device__ __forceinline__ void ldsm4(uint32_t& r0, uint32_t& r1, uint32_t& r2, uint32_t& r3,
                                      uint32_t addr) {
    asm volatile("ldmatrix.sync.aligned.m8n8.x4.shared.b16 {%0,%1,%2,%3}, [%4];"
                 : "=r"(r0), "=r"(r1), "=r"(r2), "=r"(r3) : "r"(addr));
}
__device__ __forceinline__ void mma16816(float& d0, float& d1, float& d2, float& d3,
                                         uint32_t a0, uint32_t a1, uint32_t a2, uint32_t a3,
                                         uint32_t b0, uint32_t b1) {
    asm volatile(
        "mma.sync.aligned.m16n8k16.row.col.f32.f16.f16.f32 "
        "{%0,%1,%2,%3}, {%4,%5,%6,%7}, {%8,%9}, {%0,%1,%2,%3};"
        : "+f"(d0), "+f"(d1), "+f"(d2), "+f"(d3)
        : "r"(a0), "r"(a1), "r"(a2), "r"(a3), "r"(b0), "r"(b1));
}

// ---------------- fused prep kernel ----------------
__global__ void k_prep(const float* __restrict__ em, const float* __restrict__ tr,
                       const float* __restrict__ pr) {
    __shared__ float red[256];
    const int blk = blockIdx.x, t = threadIdx.x;

    if (blk < NSTATES) {
        float x = em[blk * MSYMS + t];
        red[t] = x; __syncthreads();
        for (int s = 128; s > 0; s >>= 1) { if (t < s) red[t] = fmaxf(red[t], red[t + s]); __syncthreads(); }
        float m = red[0]; __syncthreads();
        red[t] = __expf(x - m); __syncthreads();
        for (int s = 128; s > 0; s >>= 1) { if (t < s) red[t] += red[t + s]; __syncthreads(); }
        float lse = m + __logf(red[0]);
        gLET[t * NSTATES + blk] = x - lse;
        __syncthreads();

        float x0 = tr[t * NSTATES + blk];
        float x1 = tr[(t + 256) * NSTATES + blk];
        red[t] = fmaxf(x0, x1); __syncthreads();
        for (int s = 128; s > 0; s >>= 1) { if (t < s) red[t] = fmaxf(red[t], red[t + s]); __syncthreads(); }
        float mm = red[0]; __syncthreads();
        red[t] = __expf(x0 - mm) + __expf(x1 - mm); __syncthreads();
        for (int s = 128; s > 0; s >>= 1) { if (t < s) red[t] += red[t + s]; __syncthreads(); }
        float clse = mm + __logf(red[0]);
        gPh[t * NSTATES + blk]         = __float2half_rn(__expf(x0 - clse));
        gPh[(t + 256) * NSTATES + blk] = __float2half_rn(__expf(x1 - clse));
    } else {
        float x0 = pr[t], x1 = pr[t + 256];
        red[t] = fmaxf(x0, x1); __syncthreads();
        for (int s = 128; s > 0; s >>= 1) { if (t < s) red[t] = fmaxf(red[t], red[t + s]); __syncthreads(); }
        float m = red[0]; __syncthreads();
        red[t] = __expf(x0 - m) + __expf(x1 - m); __syncthreads();
        for (int s = 128; s > 0; s >>= 1) { if (t < s) red[t] += red[t + s]; __syncthreads(); }
        float lse = m + __logf(red[0]);
        gLP[t]       = x0 - lse;
        gLP[t + 256] = x1 - lse;
    }
}

// ---------------- forward kernel (8-CTA clusters, DSMEM E exchange) ----------------
extern __shared__ char sm_raw[];

__global__ void __launch_bounds__(NT, 1) forward_kernel(const int* __restrict__ batch,
                                                        float* __restrict__ out) {
    char* sm = sm_raw;
    const uint32_t smem_base = smem_u32(sm);
    float* buf    = (float*)(sm + BUF_OFF);     // [8][16][18]
    float* sm_sc  = (float*)(sm + SC_OFF);      // [16][8]
    float* sm_mbf = (float*)(sm + MB_OFF);      // [16]
    int*   syms   = (int*)(sm + SYMS_OFF);      // [16][256]
    const uint32_t P_base  = smem_base + P_OFF;
    const uint32_t ST_base = smem_base + STATS_OFF;

    const int tid  = threadIdx.x;
    const int lane = tid & 31;
    const int w    = tid >> 5;
    const int g    = blockIdx.x >> 3;        // 0..15 batch group
    const int j    = (int)cluster_rank();    // 0..7 i-slice

    // epilogue mapping: thread owns (b2, iq..iq+3)
    const int b2 = tid >> 4;                 // 0..15
    const int iq = (tid & 15) * 4;           // 0..60
    const int gb2 = g * NB + b2;

    // warp tile: mi in 0..3 (m16), kh in 0..1 (k256 half)
    const int mi = w & 3, kh = (w >> 2) & 1;
    const int kbase = kh * 256;

    // ---------------- prologue ----------------
    // P j-slice (64 x 512 fp16) -> padded SMEM rows
    #pragma unroll
    for (int it = 0; it < 16; it++) {
        int idx = tid + NT * it;             // 0..4095
        int row = idx >> 6, c = idx & 63;
        *(uint4*)(sm + P_OFF + row * (ESTR * 2) + c * 16) =
            *(const uint4*)(&gPh[(j * MI + row) * NSTATES] + c * 8);
    }
    for (int idx = tid; idx < NB * TLEN; idx += NT)
        syms[idx] = batch[(g * NB + (idx >> 8)) * TLEN + (idx & 255)];
    __syncthreads();

    // A fragments resident in registers
    uint32_t a[16][4];
    {
        const int arow  = mi * 16 + (lane & 15);
        const int akoff = (lane >> 4) * 8;
        #pragma unroll
        for (int kk = 0; kk < 16; kk++) {
            uint32_t addr = P_base + (uint32_t)((arow * ESTR + kbase + kk * 16 + akoff) * 2);
            ldsm4(a[kk][0], a[kk][1], a[kk][2], a[kk][3], addr);
        }
    }
    // B ldmatrix per-thread offset within an E buffer
    const int brow = (lane >> 4) * 8 + (lane & 7);
    const int bk0  = ((lane >> 3) & 1) * 8 + kbase;
    const uint32_t b_off = (uint32_t)((brow * ESTR + bk0) * 2);

    // scale-table columns for this thread's fragments
    const int c0 = (lane & 3) * 2;

    // ---------------- step 0 ----------------
    {
        int sy = syms[b2 * TLEN + 0];
        float4 lt = *(const float4*)&gLET[sy * NSTATES + j * MI + iq];
        float4 lp = *(const float4*)&gLP[j * MI + iq];
        float v0 = lt.x + lp.x, v1 = lt.y + lp.y, v2 = lt.z + lp.z, v3 = lt.w + lp.w;
        float m = fmaxf(fmaxf(v0, v1), fmaxf(v2, v3));
        #pragma unroll
        for (int o = 8; o > 0; o >>= 1) m = fmaxf(m, __shfl_xor_sync(0xffffffffu, m, o));
        float e0 = __expf(v0 - m), e1 = __expf(v1 - m), e2 = __expf(v2 - m), e3 = __expf(v3 - m);
        float s = e0 + e1 + e2 + e3;
        #pragma unroll
        for (int o = 8; o > 0; o >>= 1) s += __shfl_xor_sync(0xffffffffu, s, o);
        union { __half2 h[2]; unsigned long long ull; } cv;
        cv.h[0] = __floats2half2_rn(e0, e1);
        cv.h[1] = __floats2half2_rn(e2, e3);
        uint32_t laddr = smem_base + E_OFF + 0 * EBUF_SZ + b2 * (ESTR * 2) + (j * MI + iq) * 2;
        #pragma unroll
        for (int r = 0; r < GI; r++) dsmem_st_u64(laddr, r, cv.ull);
        if ((tid & 15) == 0) {
            uint32_t sa = ST_base + 0 * 1024 + b2 * 64 + j * 8;
            #pragma unroll
            for (int r = 0; r < GI; r++) dsmem_st_pair(sa, r, m, s);
        }
        CLUSTER_ARRIVE();
    }

    // ---------------- main loop ----------------
    for (int t = 1; t < TLEN; ++t) {
        const int p = (t - 1) & 1, q = t & 1;
        const int outj = (t - 1) & 7;

        // prefetch (peer-independent) before the wait
        int sy = syms[b2 * TLEN + t];
        float4 lt = *(const float4*)&gLET[sy * NSTATES + j * MI + iq];

        CLUSTER_WAIT();

        // phase 1 (threads 0..127): scale table from local stats
        if (tid < 128) {
            int b = tid >> 3, jj = tid & 7;
            float2 pr2 = *(float2*)(sm + STATS_OFF + p * 1024 + b * 64 + jj * 8);
            float mloc = pr2.x;
            #pragma unroll
            for (int o = 4; o > 0; o >>= 1)
                mloc = fmaxf(mloc, __shfl_xor_sync(0xffffffffu, mloc, o));
            float sc = __expf(pr2.x - mloc);
            sm_sc[b * 8 + jj] = sc;
            if (jj == 0) sm_mbf[b] = mloc;
            if (j == outj) {
                float ps = sc * pr2.y;
                #pragma unroll
                for (int o = 4; o > 0; o >>= 1)
                    ps += __shfl_xor_sync(0xffffffffu, ps, o);
                if (jj == 0) out[(g * NB + b) * TLEN + (t - 1)] = mloc + __logf(ps);
            }
        }
        __syncthreads();

        // phase 2: HMMA on DSMEM-delivered E (4 accumulator sets, one per k-tile)
        const uint32_t b_addrP = smem_base + E_OFF + p * EBUF_SZ + b_off;
        float acc[4][8];
        #pragma unroll
        for (int tt = 0; tt < 4; tt++)
            #pragma unroll
            for (int z = 0; z < 8; z++) acc[tt][z] = 0.f;
        #pragma unroll
        for (int tt = 0; tt < 4; tt++) {
            #pragma unroll
            for (int ki = 0; ki < 4; ki++) {
                int kk = tt * 4 + ki;
                uint32_t r0, r1, r2, r3;
                ldsm4(r0, r1, r2, r3, b_addrP + (uint32_t)(kk * 32));
                mma16816(acc[tt][0], acc[tt][1], acc[tt][2], acc[tt][3],
                         a[kk][0], a[kk][1], a[kk][2], a[kk][3], r0, r1);
                mma16816(acc[tt][4], acc[tt][5], acc[tt][6], acc[tt][7],
                         a[kk][0], a[kk][1], a[kk][2], a[kk][3], r2, r3);
            }
        }

        // phase 3: scale-weighted combine (C = sum_j exp(m_j - m_b) * C_j)
        float f0, f1, f2, f3, f4, f5, f6, f7;
        {
            float4 s0 = *(float4*)&sm_sc[(c0)     * 8 + 4 * kh];
            float4 s1 = *(float4*)&sm_sc[(c0 + 1) * 8 + 4 * kh];
            float4 s2 = *(float4*)&sm_sc[(c0 + 8) * 8 + 4 * kh];
            float4 s3 = *(float4*)&sm_sc[(c0 + 9) * 8 + 4 * kh];
            f0 = s0.x*acc[0][0] + s0.y*acc[1][0] + s0.z*acc[2][0] + s0.w*acc[3][0];
            f1 = s1.x*acc[0][1] + s1.y*acc[1][1] + s1.z*acc[2][1] + s1.w*acc[3][1];
            f2 = s0.x*acc[0][2] + s0.y*acc[1][2] + s0.z*acc[2][2] + s0.w*acc[3][2];
            f3 = s1.x*acc[0][3] + s1.y*acc[1][3] + s1.z*acc[2][3] + s1.w*acc[3][3];
            f4 = s2.x*acc[0][4] + s2.y*acc[1][4] + s2.z*acc[2][4] + s2.w*acc[3][4];
            f5 = s3.x*acc[0][5] + s3.y*acc[1][5] + s3.z*acc[2][5] + s3.w*acc[3][5];
            f6 = s2.x*acc[0][6] + s2.y*acc[1][6] + s2.z*acc[2][6] + s2.w*acc[3][6];
            f7 = s3.x*acc[0][7] + s3.y*acc[1][7] + s3.z*acc[2][7] + s3.w*acc[3][7];
        }

        // phase 4: stash split-k partials
        {
            int r1r = lane >> 2, cc = (lane & 3) * 2;
            float* bw = &buf[w * 16 * 18];
            *(float2*)&bw[r1r * 18 + cc]           = make_float2(f0, f1);
            *(float2*)&bw[(r1r + 8) * 18 + cc]     = make_float2(f2, f3);
            *(float2*)&bw[r1r * 18 + cc + 8]       = make_float2(f4, f5);
            *(float2*)&bw[(r1r + 8) * 18 + cc + 8] = make_float2(f6, f7);
        }
        __syncthreads();

        // phase 5: epilogue — split-k add, log, +mb+em, publish E + stats via DSMEM
        {
            const int mis = iq >> 4, rbase = iq & 15;
            const float* b0p = &buf[mis * 288 + b2];
            const float* b1p = b0p + 4 * 288;
            float C0 = b0p[(rbase + 0) * 18] + b1p[(rbase + 0) * 18];
            float C1 = b0p[(rbase + 1) * 18] + b1p[(rbase + 1) * 18];
            float C2 = b0p[(rbase + 2) * 18] + b1p[(rbase + 2) * 18];
            float C3 = b0p[(rbase + 3) * 18] + b1p[(rbase + 3) * 18];
            float mbv = sm_mbf[b2];
            float v0 = __logf(C0) + mbv + lt.x;
            float v1 = __logf(C1) + mbv + lt.y;
            float v2 = __logf(C2) + mbv + lt.z;
            float v3 = __logf(C3) + mbv + lt.w;
            float m = fmaxf(fmaxf(v0, v1), fmaxf(v2, v3));
            #pragma unroll
            for (int o = 8; o > 0; o >>= 1) m = fmaxf(m, __shfl_xor_sync(0xffffffffu, m, o));
            float e0 = __expf(v0 - m), e1 = __expf(v1 - m), e2 = __expf(v2 - m), e3 = __expf(v3 - m);
            float s = e0 + e1 + e2 + e3;
            #pragma unroll
            for (int o = 8; o > 0; o >>= 1) s += __shfl_xor_sync(0xffffffffu, s, o);
            union { __half2 h[2]; unsigned long long ull; } cv;
            cv.h[0] = __floats2half2_rn(e0, e1);
            cv.h[1] = __floats2half2_rn(e2, e3);
            uint32_t laddr = smem_base + E_OFF + q * EBUF_SZ + b2 * (ESTR * 2) + (j * MI + iq) * 2;
            #pragma unroll
            for (int r = 0; r < GI; r++) dsmem_st_u64(laddr, r, cv.ull);
            if ((tid & 15) == 0) {
                uint32_t sa = ST_base + q * 1024 + b2 * 64 + j * 8;
                #pragma unroll
                for (int r = 0; r < GI; r++) dsmem_st_pair(sa, r, m, s);
            }
        }

        CLUSTER_ARRIVE();
    }

    // final column t=255 (stats buffer 1), owner j == 7
    CLUSTER_WAIT();
    if (j == 7 && tid < NB) {
        const float2* st = (const float2*)(sm + STATS_OFF + 1024 + tid * 64);
        float mb = st[0].x;
        #pragma unroll
        for (int jj = 1; jj < GI; jj++) mb = fmaxf(mb, st[jj].x);
        float ssum = 0.f;
        #pragma unroll
        for (int jj = 0; jj < GI; jj++) ssum += __expf(st[jj].x - mb) * st[jj].y;
        out[(g * NB + tid) * TLEN + (TLEN - 1)] = mb + __logf(ssum);
    }
}

// ---------------- launch ----------------
extern "C" void kernel_launch(void* const* d_in, const int* in_sizes, int n_in,
                              void* d_out, int out_size) {
    const int*   batch = (const int*)d_in[0];
    const float* em    = (const float*)d_in[1];
    const float* tr    = (const float*)d_in[2];
    const float* pr    = (const float*)d_in[3];
    float* out = (float*)d_out;

    cudaFuncSetAttribute(forward_kernel, cudaFuncAttributeMaxDynamicSharedMemorySize, SMEM_TOTAL);

    k_prep<<<NSTATES + 1, 256>>>(em, tr, pr);

    cudaLaunchConfig_t cfg = {};
    cfg.gridDim = dim3(NCTA, 1, 1);
    cfg.blockDim = dim3(NT, 1, 1);
    cfg.dynamicSmemBytes = SMEM_TOTAL;
    cfg.stream = 0;
    cudaLaunchAttribute attrs[1];
    attrs[0].id = cudaLaunchAttributeClusterDimension;
    attrs[0].val.clusterDim.x = GI;
    attrs[0].val.clusterDim.y = 1;
    attrs[0].val.clusterDim.z = 1;
    cfg.attrs = attrs;
    cfg.numAttrs = 1;
    cudaLaunchKernelEx(&cfg, forward_kernel, batch, out);
}

// round 10
// speedup vs baseline: 1.1168x; 1.1168x over previous
#include <cuda_runtime.h>
#include <cuda_fp16.h>
#include <cstdint>

#define NSTATES 512
#define MSYMS   256
#define BATCHN  256
#define TLEN    256

#define GB 16                // batch groups (clusters)
#define GI 8                 // cluster size (i-slices)
#define NB 16                // batch rows per group
#define MI 64                // states per CTA
#define NCTA (GB*GI)         // 128 CTAs
#define NT 256               // 8 warps

#define ESTR 520             // fp16 row stride (1040B)

// ---- dynamic SMEM layout (bytes) ----
#define BUF_OFF    0                     // float[8][16][18] = 9216
#define STATS_OFF  9216                  // float2 [2][16 b][8 j] = 2048
#define SC_OFF     11264                 // float [16 b][8 j] = 512
#define MB_OFF     11776                 // float[16] = 64
#define MBAR_OFF   11840                 // 2 x u64 mbarriers = 16
#define P_OFF      11904                 // 64 x 520 fp16 = 66560 (128B aligned)
#define E_OFF      78464                 // 16 x 520 fp16 = 16640 (single staging buf)
#define SYMS_OFF   95104                 // 16 x 256 int = 16384
#define SMEM_TOTAL 111488

// ---------------- device globals ----------------
__device__ __half gPh[NSTATES * NSTATES];   // column-softmax of transition, fp16
__device__ float  gLET[MSYMS * NSTATES];    // log emission transposed [sym][state]
__device__ float  gLP[NSTATES];             // log priors
__device__ __half gEh[2][BATCHN][NSTATES];  // tile-normalized E, fp16, dbl-buffered

// ---------------- PTX helpers ----------------
__device__ __forceinline__ uint32_t smem_u32(const void* p) {
    uint32_t a;
    asm("{ .reg .u64 t; cvta.to.shared.u64 t, %1; cvt.u32.u64 %0, t; }" : "=r"(a) : "l"(p));
    return a;
}
__device__ __forceinline__ uint32_t cluster_rank() {
    uint32_t r; asm("mov.u32 %0, %%cluster_ctarank;" : "=r"(r)); return r;
}
#define CLUSTER_SYNC() do { \
    asm volatile("barrier.cluster.arrive.aligned;" ::: "memory"); \
    asm volatile("barrier.cluster.wait.aligned;"   ::: "memory"); \
} while (0)

__device__ __forceinline__ void mbar_init(uint32_t mbar, uint32_t cnt) {
    asm volatile("mbarrier.init.shared.b64 [%0], %1;" :: "r"(mbar), "r"(cnt) : "memory");
}
__device__ __forceinline__ void mbar_arrive_remote(uint32_t laddr, uint32_t rank) {
    asm volatile(
        "{\n\t.reg .b32 r;\n\t"
        "mapa.shared::cluster.u32 r, %0, %1;\n\t"
        "mbarrier.arrive.release.cluster.shared::cluster.b64 _, [r];\n\t}"
        :: "r"(laddr), "r"(rank) : "memory");
}
__device__ __forceinline__ void mbar_wait(uint32_t mbar, uint32_t parity) {
    asm volatile(
        "{\n\t.reg .pred P;\n\t"
        "WL_%=:\n\t"
        "mbarrier.try_wait.parity.acquire.cluster.shared::cta.b64 P, [%0], %1, 0x989680;\n\t"
        "@!P bra WL_%=;\n\t}"
        :: "r"(mbar), "r"(parity) : "memory");
}
__device__ __forceinline__ void dsmem_st_pair(uint32_t laddr, uint32_t rank, float mx, float sx) {
    asm volatile(
        "{\n\t.reg .b32 r;\n\t"
        "mapa.shared::cluster.u32 r, %0, %1;\n\t"
        "st.shared::cluster.f32 [r], %2;\n\t"
        "st.shared::cluster.f32 [r+4], %3;\n\t}"
        :: "r"(laddr), "r"(rank), "f"(mx), "f"(sx) : "memory");
}
__device__ __forceinline__ void ldsm4(uint32_t& r0, uint32_t& r1, uint32_t& r2, uint32_t& r3,
                                      uint32_t addr) {
    asm volatile("ldmatrix.sync.aligned.m8n8.x4.shared.b16 {%0,%1,%2,%3}, [%4];"
                 : "=r"(r0), "=r"(r1), "=r"(r2), "=r"(r3) : "r"(addr));
}
__device__ __forceinline__ void mma16816(float& d0, float& d1, float& d2, float& d3,
                                         uint32_t a0, uint32_t a1, uint32_t a2, uint32_t a3,
                                         uint32_t b0, uint32_t b1) {
    asm volatile(
        "mma.sync.aligned.m16n8k16.row.col.f32.f16.f16.f32 "
        "{%0,%1,%2,%3}, {%4,%5,%6,%7}, {%8,%9}, {%0,%1,%2,%3};"
        : "+f"(d0), "+f"(d1), "+f"(d2), "+f"(d3)
        : "r"(a0), "r"(a1), "r"(a2), "r"(a3), "r"(b0), "r"(b1));
}

// ---------------- fused prep kernel ----------------
__global__ void k_prep(const float* __restrict__ em, const float* __restrict__ tr,
                       const float* __restrict__ pr) {
    __shared__ float red[256];
    const int blk = blockIdx.x, t = threadIdx.x;

    if (blk < NSTATES) {
        float x = em[blk * MSYMS + t];
        red[t] = x; __syncthreads();
        for (int s = 128; s > 0; s >>= 1) { if (t < s) red[t] = fmaxf(red[t], red[t + s]); __syncthreads(); }
        float m = red[0]; __syncthreads();
        red[t] = __expf(x - m); __syncthreads();
        for (int s = 128; s > 0; s >>= 1) { if (t < s) red[t] += red[t + s]; __syncthreads(); }
        float lse = m + __logf(red[0]);
        gLET[t * NSTATES + blk] = x - lse;
        __syncthreads();

        float x0 = tr[t * NSTATES + blk];
        float x1 = tr[(t + 256) * NSTATES + blk];
        red[t] = fmaxf(x0, x1); __syncthreads();
        for (int s = 128; s > 0; s >>= 1) { if (t < s) red[t] = fmaxf(red[t], red[t + s]); __syncthreads(); }
        float mm = red[0]; __syncthreads();
        red[t] = __expf(x0 - mm) + __expf(x1 - mm); __syncthreads();
        for (int s = 128; s > 0; s >>= 1) { if (t < s) red[t] += red[t + s]; __syncthreads(); }
        float clse = mm + __logf(red[0]);
        gPh[t * NSTATES + blk]         = __float2half_rn(__expf(x0 - clse));
        gPh[(t + 256) * NSTATES + blk] = __float2half_rn(__expf(x1 - clse));
    } else {
        float x0 = pr[t], x1 = pr[t + 256];
        red[t] = fmaxf(x0, x1); __syncthreads();
        for (int s = 128; s > 0; s >>= 1) { if (t < s) red[t] = fmaxf(red[t], red[t + s]); __syncthreads(); }
        float m = red[0]; __syncthreads();
        red[t] = __expf(x0 - m) + __expf(x1 - m); __syncthreads();
        for (int s = 128; s > 0; s >>= 1) { if (t < s) red[t] += red[t + s]; __syncthreads(); }
        float lse = m + __logf(red[0]);
        gLP[t]       = x0 - lse;
        gLP[t + 256] = x1 - lse;
    }
}

// ---------------- forward kernel ----------------
extern __shared__ char sm_raw[];

__global__ void __launch_bounds__(NT, 1) forward_kernel(const int* __restrict__ batch,
                                                        float* __restrict__ out) {
    char* sm = sm_raw;
    const uint32_t smem_base = smem_u32(sm);
    float* buf    = (float*)(sm + BUF_OFF);     // [8][16][18]
    float* sm_sc  = (float*)(sm + SC_OFF);      // [16][8]
    float* sm_mbf = (float*)(sm + MB_OFF);      // [16]
    int*   syms   = (int*)(sm + SYMS_OFF);      // [16][256]
    const uint32_t P_base  = smem_base + P_OFF;
    const uint32_t ST_base = smem_base + STATS_OFF;
    const uint32_t MBAR0   = smem_base + MBAR_OFF;

    const int tid  = threadIdx.x;
    const int lane = tid & 31;
    const int w    = tid >> 5;
    const int g    = blockIdx.x >> 3;        // 0..15 batch group
    const int j    = (int)cluster_rank();    // 0..7 i-slice

    // epilogue / copy mapping
    const int b2 = tid >> 4;                 // 0..15
    const int cpos = tid & 15;               // column position for copy
    const int iq = cpos * 4;                 // epilogue i-quad
    const int gb2 = g * NB + b2;

    // warp tile: mi in 0..3 (m16), kh in 0..1 (k256 half)
    const int mi = w & 3, kh = (w >> 2) & 1;
    const int kbase = kh * 256;

    // ---------------- prologue ----------------
    if (tid == 0) { mbar_init(MBAR0, GI); mbar_init(MBAR0 + 8, GI); }
    #pragma unroll
    for (int it = 0; it < 16; it++) {
        int idx = tid + NT * it;
        int row = idx >> 6, c = idx & 63;
        *(uint4*)(sm + P_OFF + row * (ESTR * 2) + c * 16) =
            *(const uint4*)(&gPh[(j * MI + row) * NSTATES] + c * 8);
    }
    for (int idx = tid; idx < NB * TLEN; idx += NT)
        syms[idx] = batch[(g * NB + (idx >> 8)) * TLEN + (idx & 255)];
    __syncthreads();
    CLUSTER_SYNC();   // mbarrier inits visible cluster-wide

    // A fragments resident in registers
    uint32_t a[16][4];
    {
        const int arow  = mi * 16 + (lane & 15);
        const int akoff = (lane >> 4) * 8;
        #pragma unroll
        for (int kk = 0; kk < 16; kk++) {
            uint32_t addr = P_base + (uint32_t)((arow * ESTR + kbase + kk * 16 + akoff) * 2);
            ldsm4(a[kk][0], a[kk][1], a[kk][2], a[kk][3], addr);
        }
    }
    // B ldmatrix per-thread offset within E staging
    const int brow = (lane >> 4) * 8 + (lane & 7);
    const int bk0  = ((lane >> 3) & 1) * 8 + kbase;
    const uint32_t b_addr = smem_base + E_OFF + (uint32_t)((brow * ESTR + bk0) * 2);
    const int c0 = (lane & 3) * 2;

    // ---------------- step 0 ----------------
    {
        int sy = syms[b2 * TLEN + 0];
        float4 lt = *(const float4*)&gLET[sy * NSTATES + j * MI + iq];
        float4 lp = *(const float4*)&gLP[j * MI + iq];
        float v0 = lt.x + lp.x, v1 = lt.y + lp.y, v2 = lt.z + lp.z, v3 = lt.w + lp.w;
        float m = fmaxf(fmaxf(v0, v1), fmaxf(v2, v3));
        #pragma unroll
        for (int o = 8; o > 0; o >>= 1) m = fmaxf(m, __shfl_xor_sync(0xffffffffu, m, o));
        float e0 = __expf(v0 - m), e1 = __expf(v1 - m), e2 = __expf(v2 - m), e3 = __expf(v3 - m);
        float s = e0 + e1 + e2 + e3;
        #pragma unroll
        for (int o = 8; o > 0; o >>= 1) s += __shfl_xor_sync(0xffffffffu, s, o);
        union { __half2 h[2]; uint2 uu; } cv;
        cv.h[0] = __floats2half2_rn(e0, e1);
        cv.h[1] = __floats2half2_rn(e2, e3);
        __stcg((uint2*)&gEh[0][gb2][j * MI + iq], cv.uu);
        if (cpos == 0) {
            uint32_t sa = ST_base + 0 * 1024 + b2 * 64 + j * 8;
            #pragma unroll
            for (int r = 0; r < GI; r++) dsmem_st_pair(sa, r, m, s);
        }
        __syncthreads();
        if (tid < GI) mbar_arrive_remote(MBAR0, (uint32_t)tid);   // bar[0], step 0
    }

    // ---------------- main loop ----------------
    for (int t = 1; t < TLEN; ++t) {
        const int p = (t - 1) & 1, q = t & 1;
        const int outj = (t - 1) & 7;

        // prefetch before the wait
        int sy = syms[b2 * TLEN + t];
        float4 lt = *(const float4*)&gLET[sy * NSTATES + j * MI + iq];

        // wait: publishes of step t-1 (bar[(t-1)&1], phase ((t-1)>>1)&1)
        mbar_wait(MBAR0 + 8 * ((t - 1) & 1), ((t - 1) >> 1) & 1);

        // phase 0: E copy gmem(L2) -> SMEM staging (no scale dependency)
        uint4 eraw[4];
        {
            const __half* esrc = &gEh[p][g * NB + b2][0];
            #pragma unroll
            for (int cc = 0; cc < 4; cc++)
                eraw[cc] = __ldcg((const uint4*)(esrc + (cpos + 16 * cc) * 8));
        }

        // phase 1 (threads 0..127): scale table from local (DSMEM-delivered) stats
        if (tid < 128) {
            int b = tid >> 3, jj = tid & 7;
            float2 pr2 = *(float2*)(sm + STATS_OFF + p * 1024 + b * 64 + jj * 8);
            float mloc = pr2.x;
            #pragma unroll
            for (int o = 4; o > 0; o >>= 1)
                mloc = fmaxf(mloc, __shfl_xor_sync(0xffffffffu, mloc, o));
            float sc = __expf(pr2.x - mloc);
            sm_sc[b * 8 + jj] = sc;
            if (jj == 0) sm_mbf[b] = mloc;
            if (j == outj) {
                float ps = sc * pr2.y;
                #pragma unroll
                for (int o = 4; o > 0; o >>= 1)
                    ps += __shfl_xor_sync(0xffffffffu, ps, o);
                if (jj == 0) out[(g * NB + b) * TLEN + (t - 1)] = mloc + __logf(ps);
            }
        }

        // store staged E
        {
            char* edst = sm + E_OFF + b2 * (ESTR * 2);
            #pragma unroll
            for (int cc = 0; cc < 4; cc++)
                *(uint4*)(edst + (cpos + 16 * cc) * 16) = eraw[cc];
        }
        __syncthreads();

        // phase 2: HMMA, 4 accumulator sets (one per producer k-tile pair)
        float acc[4][8];
        #pragma unroll
        for (int tt = 0; tt < 4; tt++)
            #pragma unroll
            for (int z = 0; z < 8; z++) acc[tt][z] = 0.f;
        #pragma unroll
        for (int tt = 0; tt < 4; tt++) {
            #pragma unroll
            for (int ki = 0; ki < 4; ki++) {
                int kk = tt * 4 + ki;
                uint32_t r0, r1, r2, r3;
                ldsm4(r0, r1, r2, r3, b_addr + (uint32_t)(kk * 32));
                mma16816(acc[tt][0], acc[tt][1], acc[tt][2], acc[tt][3],
                         a[kk][0], a[kk][1], a[kk][2], a[kk][3], r0, r1);
                mma16816(acc[tt][4], acc[tt][5], acc[tt][6], acc[tt][7],
                         a[kk][0], a[kk][1], a[kk][2], a[kk][3], r2, r3);
            }
        }

        // phase 3: scale-weighted combine
        float f0, f1, f2, f3, f4, f5, f6, f7;
        {
            float4 s0 = *(float4*)&sm_sc[(c0)     * 8 + 4 * kh];
            float4 s1 = *(float4*)&sm_sc[(c0 + 1) * 8 + 4 * kh];
            float4 s2 = *(float4*)&sm_sc[(c0 + 8) * 8 + 4 * kh];
            float4 s3 = *(float4*)&sm_sc[(c0 + 9) * 8 + 4 * kh];
            f0 = s0.x*acc[0][0] + s0.y*acc[1][0] + s0.z*acc[2][0] + s0.w*acc[3][0];
            f1 = s1.x*acc[0][1] + s1.y*acc[1][1] + s1.z*acc[2][1] + s1.w*acc[3][1];
            f2 = s0.x*acc[0][2] + s0.y*acc[1][2] + s0.z*acc[2][2] + s0.w*acc[3][2];
            f3 = s1.x*acc[0][3] + s1.y*acc[1][3] + s1.z*acc[2][3] + s1.w*acc[3][3];
            f4 = s2.x*acc[0][4] + s2.y*acc[1][4] + s2.z*acc[2][4] + s2.w*acc[3][4];
            f5 = s3.x*acc[0][5] + s3.y*acc[1][5] + s3.z*acc[2][5] + s3.w*acc[3][5];
            f6 = s2.x*acc[0][6] + s2.y*acc[1][6] + s2.z*acc[2][6] + s2.w*acc[3][6];
            f7 = s3.x*acc[0][7] + s3.y*acc[1][7] + s3.z*acc[2][7] + s3.w*acc[3][7];
        }

        // phase 4: stash split-k partials
        {
            int r1r = lane >> 2, cc = (lane & 3) * 2;
            float* bw = &buf[w * 16 * 18];
            *(float2*)&bw[r1r * 18 + cc]           = make_float2(f0, f1);
            *(float2*)&bw[(r1r + 8) * 18 + cc]     = make_float2(f2, f3);
            *(float2*)&bw[r1r * 18 + cc + 8]       = make_float2(f4, f5);
            *(float2*)&bw[(r1r + 8) * 18 + cc + 8] = make_float2(f6, f7);
        }
        __syncthreads();

        // phase 5: epilogue — split-k add, log, +mb+em, publish E + stats
        {
            const int mis = iq >> 4, rbase = iq & 15;
            const float* b0p = &buf[mis * 288 + b2];
            const float* b1p = b0p + 4 * 288;
            float C0 = b0p[(rbase + 0) * 18] + b1p[(rbase + 0) * 18];
            float C1 = b0p[(rbase + 1) * 18] + b1p[(rbase + 1) * 18];
            float C2 = b0p[(rbase + 2) * 18] + b1p[(rbase + 2) * 18];
            float C3 = b0p[(rbase + 3) * 18] + b1p[(rbase + 3) * 18];
            float mbv = sm_mbf[b2];
            float v0 = __logf(C0) + mbv + lt.x;
            float v1 = __logf(C1) + mbv + lt.y;
            float v2 = __logf(C2) + mbv + lt.z;
            float v3 = __logf(C3) + mbv + lt.w;
            float m = fmaxf(fmaxf(v0, v1), fmaxf(v2, v3));
            #pragma unroll
            for (int o = 8; o > 0; o >>= 1) m = fmaxf(m, __shfl_xor_sync(0xffffffffu, m, o));
            float e0 = __expf(v0 - m), e1 = __expf(v1 - m), e2 = __expf(v2 - m), e3 = __expf(v3 - m);
            float s = e0 + e1 + e2 + e3;
            #pragma unroll
            for (int o = 8; o > 0; o >>= 1) s += __shfl_xor_sync(0xffffffffu, s, o);
            union { __half2 h[2]; uint2 uu; } cv;
            cv.h[0] = __floats2half2_rn(e0, e1);
            cv.h[1] = __floats2half2_rn(e2, e3);
            __stcg((uint2*)&gEh[q][gb2][j * MI + iq], cv.uu);
            if (cpos == 0) {
                uint32_t sa = ST_base + q * 1024 + b2 * 64 + j * 8;
                #pragma unroll
                for (int r = 0; r < GI; r++) dsmem_st_pair(sa, r, m, s);
            }
        }

        __syncthreads();
        if (tid < GI) mbar_arrive_remote(MBAR0 + 8 * (t & 1), (uint32_t)tid);
    }

    // final column t=255: stats buffer 1, publishes on bar[1] phase 1
    if (j == 7) {
        mbar_wait(MBAR0 + 8, ((TLEN - 1) >> 1) & 1);
        if (tid < NB) {
            const float2* st = (const float2*)(sm + STATS_OFF + 1024 + tid * 64);
            float mb = st[0].x;
            #pragma unroll
            for (int jj = 1; jj < GI; jj++) mb = fmaxf(mb, st[jj].x);
            float ssum = 0.f;
            #pragma unroll
            for (int jj = 0; jj < GI; jj++) ssum += __expf(st[jj].x - mb) * st[jj].y;
            out[(g * NB + tid) * TLEN + (TLEN - 1)] = mb + __logf(ssum);
        }
        __syncthreads();
    }
    CLUSTER_SYNC();   // no CTA exits while peers' remote ops may be in flight
}

// ---------------- launch ----------------
extern "C" void kernel_launch(void* const* d_in, const int* in_sizes, int n_in,
                              void* d_out, int out_size) {
    const int*   batch = (const int*)d_in[0];
    const float* em    = (const float*)d_in[1];
    const float* tr    = (const float*)d_in[2];
    const float* pr    = (const float*)d_in[3];
    float* out = (float*)d_out;

    cudaFuncSetAttribute(forward_kernel, cudaFuncAttributeMaxDynamicSharedMemorySize, SMEM_TOTAL);

    k_prep<<<NSTATES + 1, 256>>>(em, tr, pr);

    cudaLaunchConfig_t cfg = {};
    cfg.gridDim = dim3(NCTA, 1, 1);
    cfg.blockDim = dim3(NT, 1, 1);
    cfg.dynamicSmemBytes = SMEM_TOTAL;
    cfg.stream = 0;
    cudaLaunchAttribute attrs[1];
    attrs[0].id = cudaLaunchAttributeClusterDimension;
    attrs[0].val.clusterDim.x = GI;
    attrs[0].val.clusterDim.y = 1;
    attrs[0].val.clusterDim.z = 1;
    cfg.attrs = attrs;
    cfg.numAttrs = 1;
    cudaLaunchKernelEx(&cfg, forward_kernel, batch, out);
}

// round 11
// speedup vs baseline: 2.6932x; 2.4115x over previous
#include <cuda_runtime.h>
#include <cuda_fp16.h>
#include <cstdint>

#define NSTATES 512
#define MSYMS   256
#define BATCHN  256
#define TLEN    256

#define GB 32                // batch groups (clusters)
#define GI 4                 // cluster size (i-slices)
#define NBg 8                // batch rows per group
#define MI 128               // states per CTA
#define NCTA (GB*GI)         // 128 CTAs
#define NT 256               // 8 warps

#define ESTR 520             // fp16 row stride (1040B)

// ---- dynamic SMEM layout (bytes) ----
#define BUF_OFF    0                     // 8 tiles x 162 floats = 5184
#define SM_M_OFF   5248                  // float [2][8][4] = 256
#define SM_S_OFF   5504                  // float [2][8][4] = 256
#define P_OFF      5760                  // 128 x 520 fp16 = 133120
#define E_OFF      138880                // 8 x 520 fp16 = 8320
#define SYMS_OFF   147200                // 8 x 256 int = 8192
#define SMEM_TOTAL 155392

// ---------------- device globals ----------------
__device__ __half gPh[NSTATES * NSTATES];   // column-softmax of transition, fp16
__device__ float  gLET[MSYMS * NSTATES];    // log emission transposed [sym][state]
__device__ float  gLP[NSTATES];             // log priors
__device__ __half gEh[2][BATCHN][NSTATES];  // scaled E, fp16, dbl-buffered

// ---------------- PTX helpers ----------------
__device__ __forceinline__ uint32_t smem_u32(const void* p) {
    uint32_t a;
    asm("{ .reg .u64 t; cvta.to.shared.u64 t, %1; cvt.u32.u64 %0, t; }" : "=r"(a) : "l"(p));
    return a;
}
__device__ __forceinline__ uint32_t cluster_rank() {
    uint32_t r; asm("mov.u32 %0, %%cluster_ctarank;" : "=r"(r)); return r;
}
#define CLUSTER_ARRIVE() asm volatile("barrier.cluster.arrive.aligned;" ::: "memory")
#define CLUSTER_WAIT()   asm volatile("barrier.cluster.wait.aligned;"   ::: "memory")

// push (m,s) into peer rank's sm_m / sm_s (sm_s = sm_m + 256B, offset preserved by mapa)
__device__ __forceinline__ void dsmem_st_ms(uint32_t laddr_m, uint32_t rank, float mx, float sx) {
    asm volatile(
        "{\n\t.reg .b32 r;\n\t"
        "mapa.shared::cluster.u32 r, %0, %1;\n\t"
        "st.shared::cluster.f32 [r], %2;\n\t"
        "st.shared::cluster.f32 [r+256], %3;\n\t}"
        :: "r"(laddr_m), "r"(rank), "f"(mx), "f"(sx) : "memory");
}
__device__ __forceinline__ void ldsm4(uint32_t& r0, uint32_t& r1, uint32_t& r2, uint32_t& r3,
                                      uint32_t addr) {
    asm volatile("ldmatrix.sync.aligned.m8n8.x4.shared.b16 {%0,%1,%2,%3}, [%4];"
                 : "=r"(r0), "=r"(r1), "=r"(r2), "=r"(r3) : "r"(addr));
}
__device__ __forceinline__ void ldsm2(uint32_t& r0, uint32_t& r1, uint32_t addr) {
    asm volatile("ldmatrix.sync.aligned.m8n8.x2.shared.b16 {%0,%1}, [%2];"
                 : "=r"(r0), "=r"(r1) : "r"(addr));
}
__device__ __forceinline__ void mma16816(float& d0, float& d1, float& d2, float& d3,
                                         uint32_t a0, uint32_t a1, uint32_t a2, uint32_t a3,
                                         uint32_t b0, uint32_t b1) {
    asm volatile(
        "mma.sync.aligned.m16n8k16.row.col.f32.f16.f16.f32 "
        "{%0,%1,%2,%3}, {%4,%5,%6,%7}, {%8,%9}, {%0,%1,%2,%3};"
        : "+f"(d0), "+f"(d1), "+f"(d2), "+f"(d3)
        : "r"(a0), "r"(a1), "r"(a2), "r"(a3), "r"(b0), "r"(b1));
}

// ---------------- fused prep kernel ----------------
__global__ void k_prep(const float* __restrict__ em, const float* __restrict__ tr,
                       const float* __restrict__ pr) {
    __shared__ float red[256];
    const int blk = blockIdx.x, t = threadIdx.x;

    if (blk < NSTATES) {
        float x = em[blk * MSYMS + t];
        red[t] = x; __syncthreads();
        for (int s = 128; s > 0; s >>= 1) { if (t < s) red[t] = fmaxf(red[t], red[t + s]); __syncthreads(); }
        float m = red[0]; __syncthreads();
        red[t] = __expf(x - m); __syncthreads();
        for (int s = 128; s > 0; s >>= 1) { if (t < s) red[t] += red[t + s]; __syncthreads(); }
        float lse = m + __logf(red[0]);
        gLET[t * NSTATES + blk] = x - lse;
        __syncthreads();

        float x0 = tr[t * NSTATES + blk];
        float x1 = tr[(t + 256) * NSTATES + blk];
        red[t] = fmaxf(x0, x1); __syncthreads();
        for (int s = 128; s > 0; s >>= 1) { if (t < s) red[t] = fmaxf(red[t], red[t + s]); __syncthreads(); }
        float mm = red[0]; __syncthreads();
        red[t] = __expf(x0 - mm) + __expf(x1 - mm); __syncthreads();
        for (int s = 128; s > 0; s >>= 1) { if (t < s) red[t] += red[t + s]; __syncthreads(); }
        float clse = mm + __logf(red[0]);
        gPh[t * NSTATES + blk]         = __float2half_rn(__expf(x0 - clse));
        gPh[(t + 256) * NSTATES + blk] = __float2half_rn(__expf(x1 - clse));
    } else {
        float x0 = pr[t], x1 = pr[t + 256];
        red[t] = fmaxf(x0, x1); __syncthreads();
        for (int s = 128; s > 0; s >>= 1) { if (t < s) red[t] = fmaxf(red[t], red[t + s]); __syncthreads(); }
        float m = red[0]; __syncthreads();
        red[t] = __expf(x0 - m) + __expf(x1 - m); __syncthreads();
        for (int s = 128; s > 0; s >>= 1) { if (t < s) red[t] += red[t + s]; __syncthreads(); }
        float lse = m + __logf(red[0]);
        gLP[t]       = x0 - lse;
        gLP[t + 256] = x1 - lse;
    }
}

// ---------------- forward kernel (4-CTA clusters) ----------------
extern __shared__ char sm_raw[];

__global__ void __launch_bounds__(NT, 1) forward_kernel(const int* __restrict__ batch,
                                                        float* __restrict__ out) {
    char* sm = sm_raw;
    const uint32_t smem_base = smem_u32(sm);
    float* buf  = (float*)(sm + BUF_OFF);
    int*   syms = (int*)(sm + SYMS_OFF);      // [8][256]
    const uint32_t P_base = smem_base + P_OFF;
    const uint32_t E_base = smem_base + E_OFF;
    const uint32_t SMM    = smem_base + SM_M_OFF;

    const int tid  = threadIdx.x;
    const int lane = tid & 31;
    const int w    = tid >> 5;               // warp = m-tile = batch row
    const int g    = blockIdx.x >> 2;        // 0..31 batch group
    const int j    = (int)cluster_rank();    // 0..3 i-slice
    const int gb   = g * NBg + w;            // global batch row for this warp

    // ---------------- prologue ----------------
    // P j-slice (128 x 512 fp16) -> padded SMEM rows
    #pragma unroll
    for (int it = 0; it < 32; it++) {
        int idx = tid + NT * it;              // 0..8191 (16B chunks)
        int row = idx >> 6, c = idx & 63;
        *(uint4*)(sm + P_OFF + row * (ESTR * 2) + c * 16) =
            *(const uint4*)(&gPh[(j * MI + row) * NSTATES] + c * 8);
    }
    for (int idx = tid; idx < NBg * TLEN; idx += NT)
        syms[idx] = batch[(g * NBg + (idx >> 8)) * TLEN + (idx & 255)];
    __syncthreads();

    // A fragments resident in registers: warp w = m-tile w, full K=512
    uint32_t a[32][4];
    {
        const int arow  = w * 16 + (lane & 15);
        const int akoff = (lane >> 4) * 8;
        #pragma unroll
        for (int kk = 0; kk < 32; kk++) {
            uint32_t addr = P_base + (uint32_t)((arow * ESTR + kk * 16 + akoff) * 2);
            ldsm4(a[kk][0], a[kk][1], a[kk][2], a[kk][3], addr);
        }
    }
    // B ldmatrix per-thread address (rows = 8 batch rows, k halves)
    const uint32_t b_addr = E_base + (uint32_t)(((lane & 7) * ESTR + ((lane >> 3) & 1) * 8) * 2);

    // ---------------- step 0 ----------------
    {
        int sy = syms[w * TLEN + 0];
        float4 lt = *(const float4*)&gLET[sy * NSTATES + j * MI + lane * 4];
        float4 lp = *(const float4*)&gLP[j * MI + lane * 4];
        float v0 = lt.x + lp.x, v1 = lt.y + lp.y, v2 = lt.z + lp.z, v3 = lt.w + lp.w;
        float m = fmaxf(fmaxf(v0, v1), fmaxf(v2, v3));
        #pragma unroll
        for (int o = 16; o > 0; o >>= 1) m = fmaxf(m, __shfl_xor_sync(0xffffffffu, m, o));
        float e0 = __expf(v0 - m), e1 = __expf(v1 - m), e2 = __expf(v2 - m), e3 = __expf(v3 - m);
        float s = e0 + e1 + e2 + e3;
        #pragma unroll
        for (int o = 16; o > 0; o >>= 1) s += __shfl_xor_sync(0xffffffffu, s, o);
        union { __half2 h[2]; uint2 uu; } cv;
        cv.h[0] = __floats2half2_rn(e0, e1);
        cv.h[1] = __floats2half2_rn(e2, e3);
        __stcg((uint2*)&gEh[0][gb][j * MI + lane * 4], cv.uu);
        if (lane == 0) {
            uint32_t la = SMM + (0 * 8 + w) * 16 + j * 4;
            #pragma unroll
            for (int r = 0; r < GI; r++) dsmem_st_ms(la, (uint32_t)r, m, s);
        }
        CLUSTER_ARRIVE();
    }

    // ---------------- main loop ----------------
    for (int t = 1; t < TLEN; ++t) {
        const int p = (t - 1) & 1, q = t & 1;
        const int outj = (t - 1) & 3;

        // prefetch before the wait
        int sy = syms[w * TLEN + t];
        float4 lt = *(const float4*)&gLET[sy * NSTATES + j * MI + lane * 4];

        CLUSTER_WAIT();

        // E raw loads (L2) — 2 chunks of 16B per thread for row w
        const __half* esrc = &gEh[p][gb][0];
        uint4 er0 = __ldcg((const uint4*)(esrc + lane * 8));
        uint4 er1 = __ldcg((const uint4*)(esrc + (lane + 32) * 8));

        // per-thread stats for row w (16B LDS)
        float4 mv = *(float4*)(sm + SM_M_OFF + p * 128 + w * 16);
        float mloc = fmaxf(fmaxf(mv.x, mv.y), fmaxf(mv.z, mv.w));
        float sca = __expf(((lane >> 4) ? mv.y : mv.x) - mloc);   // tile lane>>4
        float scb = __expf(((lane >> 4) ? mv.w : mv.z) - mloc);   // tile (lane>>4)+2

        // rotating out-column owner (one lane per warp)
        if (j == outj && lane == 0) {
            float4 sv = *(float4*)(sm + SM_S_OFF + p * 128 + w * 16);
            float ps = __expf(mv.x - mloc) * sv.x + __expf(mv.y - mloc) * sv.y
                     + __expf(mv.z - mloc) * sv.z + __expf(mv.w - mloc) * sv.w;
            out[gb * TLEN + (t - 1)] = mloc + __logf(ps);
        }

        // stage scaled E into padded SMEM row w
        {
            char* edst = sm + E_OFF + w * (ESTR * 2);
            __half2 h2a = __half2half2(__float2half_rn(sca));
            __half2 h2b = __half2half2(__float2half_rn(scb));
            __half2* hp0 = (__half2*)&er0;
            __half2* hp1 = (__half2*)&er1;
            #pragma unroll
            for (int z = 0; z < 4; z++) { hp0[z] = __hmul2(hp0[z], h2a); hp1[z] = __hmul2(hp1[z], h2b); }
            *(uint4*)(edst + lane * 16)        = er0;
            *(uint4*)(edst + (lane + 32) * 16) = er1;
        }
        __syncthreads();

        // HMMA: m16 x n8 x K512, two interleaved accumulator sets
        float aA0 = 0.f, aA1 = 0.f, aA2 = 0.f, aA3 = 0.f;
        float aB0 = 0.f, aB1 = 0.f, aB2 = 0.f, aB3 = 0.f;
        #pragma unroll
        for (int kk = 0; kk < 32; kk += 2) {
            uint32_t b0, b1, c0, c1;
            ldsm2(b0, b1, b_addr + (uint32_t)(kk * 32));
            ldsm2(c0, c1, b_addr + (uint32_t)((kk + 1) * 32));
            mma16816(aA0, aA1, aA2, aA3, a[kk][0], a[kk][1], a[kk][2], a[kk][3], b0, b1);
            mma16816(aB0, aB1, aB2, aB3, a[kk+1][0], a[kk+1][1], a[kk+1][2], a[kk+1][3], c0, c1);
        }
        float f0 = aA0 + aB0, f1 = aA1 + aB1, f2 = aA2 + aB2, f3 = aA3 + aB3;

        // stash m-tile partials: buf[w][row][col], stride 162 per tile, 10 per row
        {
            float* bw = &buf[w * 162];
            int r = lane >> 2, c = (lane & 3) * 2;
            *(float2*)&bw[r * 10 + c]       = make_float2(f0, f1);
            *(float2*)&bw[(r + 8) * 10 + c] = make_float2(f2, f3);
        }
        __syncthreads();

        // epilogue: warp w = batch row w, thread owns i = lane*4 .. +3
        {
            int til = lane >> 2, rb = (lane & 3) * 4;
            const float* bp = &buf[til * 162 + w];
            float C0 = bp[(rb + 0) * 10];
            float C1 = bp[(rb + 1) * 10];
            float C2 = bp[(rb + 2) * 10];
            float C3 = bp[(rb + 3) * 10];
            float v0 = __logf(C0) + mloc + lt.x;
            float v1 = __logf(C1) + mloc + lt.y;
            float v2 = __logf(C2) + mloc + lt.z;
            float v3 = __logf(C3) + mloc + lt.w;
            float m = fmaxf(fmaxf(v0, v1), fmaxf(v2, v3));
            #pragma unroll
            for (int o = 16; o > 0; o >>= 1) m = fmaxf(m, __shfl_xor_sync(0xffffffffu, m, o));
            float e0 = __expf(v0 - m), e1 = __expf(v1 - m), e2 = __expf(v2 - m), e3 = __expf(v3 - m);
            float s = e0 + e1 + e2 + e3;
            #pragma unroll
            for (int o = 16; o > 0; o >>= 1) s += __shfl_xor_sync(0xffffffffu, s, o);
            union { __half2 h[2]; uint2 uu; } cv;
            cv.h[0] = __floats2half2_rn(e0, e1);
            cv.h[1] = __floats2half2_rn(e2, e3);
            __stcg((uint2*)&gEh[q][gb][j * MI + lane * 4], cv.uu);
            if (lane == 0) {
                uint32_t la = SMM + (q * 8 + w) * 16 + j * 4;
                #pragma unroll
                for (int r = 0; r < GI; r++) dsmem_st_ms(la, (uint32_t)r, m, s);
            }
        }

        CLUSTER_ARRIVE();
    }

    // final column t = 255 (stats buffer 1), owner j == 3
    CLUSTER_WAIT();
    if (j == 3 && tid < NBg) {
        float4 mv = *(float4*)(sm + SM_M_OFF + 128 + tid * 16);
        float4 sv = *(float4*)(sm + SM_S_OFF + 128 + tid * 16);
        float mb = fmaxf(fmaxf(mv.x, mv.y), fmaxf(mv.z, mv.w));
        float ss = __expf(mv.x - mb) * sv.x + __expf(mv.y - mb) * sv.y
                 + __expf(mv.z - mb) * sv.z + __expf(mv.w - mb) * sv.w;
        out[(g * NBg + tid) * TLEN + (TLEN - 1)] = mb + __logf(ss);
    }
}

// ---------------- launch ----------------
extern "C" void kernel_launch(void* const* d_in, const int* in_sizes, int n_in,
                              void* d_out, int out_size) {
    const int*   batch = (const int*)d_in[0];
    const float* em    = (const float*)d_in[1];
    const float* tr    = (const float*)d_in[2];
    const float* pr    = (const float*)d_in[3];
    float* out = (float*)d_out;

    cudaFuncSetAttribute(forward_kernel, cudaFuncAttributeMaxDynamicSharedMemorySize, SMEM_TOTAL);

    k_prep<<<NSTATES + 1, 256>>>(em, tr, pr);

    cudaLaunchConfig_t cfg = {};
    cfg.gridDim = dim3(NCTA, 1, 1);
    cfg.blockDim = dim3(NT, 1, 1);
    cfg.dynamicSmemBytes = SMEM_TOTAL;
    cfg.stream = 0;
    cudaLaunchAttribute attrs[1];
    attrs[0].id = cudaLaunchAttributeClusterDimension;
    attrs[0].val.clusterDim.x = GI;
    attrs[0].val.clusterDim.y = 1;
    attrs[0].val.clusterDim.z = 1;
    cfg.attrs = attrs;
    cfg.numAttrs = 1;
    cudaLaunchKernelEx(&cfg, forward_kernel, batch, out);
}

// round 12
// speedup vs baseline: 2.7508x; 1.0214x over previous
#include <cuda_runtime.h>
#include <cuda_fp16.h>
#include <cstdint>

#define NSTATES 512
#define MSYMS   256
#define BATCHN  256
#define TLEN    256

#define GB 32                // batch groups (clusters)
#define GI 4                 // cluster size (i-slices)
#define NBg 8                // batch rows per group
#define MI 128               // states per CTA
#define NCTA (GB*GI)         // 128 CTAs
#define NT 256               // 8 warps

#define ESTR 520             // fp16 row stride (1040B)

// ---- dynamic SMEM layout (bytes) ----
#define BUF_OFF    0                     // 8 tiles x 162 floats = 5184
#define SM_M_OFF   5248                  // float [2][8][4] = 256
#define SM_S_OFF   5504                  // float [2][8][4] = 256
#define P_OFF      5760                  // 128 x 520 fp16 = 133120
#define E_OFF      138880                // 8 x 520 fp16 = 8320
#define SYMS_OFF   147200                // 8 x 256 int = 8192
#define SMEM_TOTAL 155392

// ---------------- device globals ----------------
__device__ __half gPh[NSTATES * NSTATES];   // column-softmax of transition, fp16
__device__ float  gET[MSYMS * NSTATES];     // emission PROBS transposed [sym][state]
__device__ float  gPr[NSTATES];             // prior PROBS
__device__ __half gEh[2][BATCHN][NSTATES];  // scaled E, fp16, dbl-buffered

// ---------------- PTX helpers ----------------
__device__ __forceinline__ uint32_t smem_u32(const void* p) {
    uint32_t a;
    asm("{ .reg .u64 t; cvta.to.shared.u64 t, %1; cvt.u32.u64 %0, t; }" : "=r"(a) : "l"(p));
    return a;
}
__device__ __forceinline__ uint32_t cluster_rank() {
    uint32_t r; asm("mov.u32 %0, %%cluster_ctarank;" : "=r"(r)); return r;
}
#define CLUSTER_ARRIVE() asm volatile("barrier.cluster.arrive.aligned;" ::: "memory")
#define CLUSTER_WAIT()   asm volatile("barrier.cluster.wait.aligned;"   ::: "memory")

// push (m,s) into peer rank's sm_m / sm_s (sm_s = sm_m + 256B)
__device__ __forceinline__ void dsmem_st_ms(uint32_t laddr_m, uint32_t rank, float mx, float sx) {
    asm volatile(
        "{\n\t.reg .b32 r;\n\t"
        "mapa.shared::cluster.u32 r, %0, %1;\n\t"
        "st.shared::cluster.f32 [r], %2;\n\t"
        "st.shared::cluster.f32 [r+256], %3;\n\t}"
        :: "r"(laddr_m), "r"(rank), "f"(mx), "f"(sx) : "memory");
}
__device__ __forceinline__ void ldsm4(uint32_t& r0, uint32_t& r1, uint32_t& r2, uint32_t& r3,
                                      uint32_t addr) {
    asm volatile("ldmatrix.sync.aligned.m8n8.x4.shared.b16 {%0,%1,%2,%3}, [%4];"
                 : "=r"(r0), "=r"(r1), "=r"(r2), "=r"(r3) : "r"(addr));
}
__device__ __forceinline__ void mma16816(float& d0, float& d1, float& d2, float& d3,
                                         uint32_t a0, uint32_t a1, uint32_t a2, uint32_t a3,
                                         uint32_t b0, uint32_t b1) {
    asm volatile(
        "mma.sync.aligned.m16n8k16.row.col.f32.f16.f16.f32 "
        "{%0,%1,%2,%3}, {%4,%5,%6,%7}, {%8,%9}, {%0,%1,%2,%3};"
        : "+f"(d0), "+f"(d1), "+f"(d2), "+f"(d3)
        : "r"(a0), "r"(a1), "r"(a2), "r"(a3), "r"(b0), "r"(b1));
}

// ---------------- fused prep kernel ----------------
__global__ void k_prep(const float* __restrict__ em, const float* __restrict__ tr,
                       const float* __restrict__ pr) {
    __shared__ float red[256];
    const int blk = blockIdx.x, t = threadIdx.x;

    if (blk < NSTATES) {
        float x = em[blk * MSYMS + t];
        red[t] = x; __syncthreads();
        for (int s = 128; s > 0; s >>= 1) { if (t < s) red[t] = fmaxf(red[t], red[t + s]); __syncthreads(); }
        float m = red[0]; __syncthreads();
        float e = __expf(x - m);
        red[t] = e; __syncthreads();
        for (int s = 128; s > 0; s >>= 1) { if (t < s) red[t] += red[t + s]; __syncthreads(); }
        gET[t * NSTATES + blk] = __fdividef(e, red[0]);   // emission prob
        __syncthreads();

        float x0 = tr[t * NSTATES + blk];
        float x1 = tr[(t + 256) * NSTATES + blk];
        red[t] = fmaxf(x0, x1); __syncthreads();
        for (int s = 128; s > 0; s >>= 1) { if (t < s) red[t] = fmaxf(red[t], red[t + s]); __syncthreads(); }
        float mm = red[0]; __syncthreads();
        red[t] = __expf(x0 - mm) + __expf(x1 - mm); __syncthreads();
        for (int s = 128; s > 0; s >>= 1) { if (t < s) red[t] += red[t + s]; __syncthreads(); }
        float clse = mm + __logf(red[0]);
        gPh[t * NSTATES + blk]         = __float2half_rn(__expf(x0 - clse));
        gPh[(t + 256) * NSTATES + blk] = __float2half_rn(__expf(x1 - clse));
    } else {
        float x0 = pr[t], x1 = pr[t + 256];
        red[t] = fmaxf(x0, x1); __syncthreads();
        for (int s = 128; s > 0; s >>= 1) { if (t < s) red[t] = fmaxf(red[t], red[t + s]); __syncthreads(); }
        float m = red[0]; __syncthreads();
        float e0 = __expf(x0 - m), e1 = __expf(x1 - m);
        red[t] = e0 + e1; __syncthreads();
        for (int s = 128; s > 0; s >>= 1) { if (t < s) red[t] += red[t + s]; __syncthreads(); }
        float inv = __fdividef(1.f, red[0]);
        gPr[t]       = e0 * inv;                          // prior prob
        gPr[t + 256] = e1 * inv;
    }
}

// ---------------- forward kernel (4-CTA clusters) ----------------
extern __shared__ char sm_raw[];

__global__ void __launch_bounds__(NT, 1) forward_kernel(const int* __restrict__ batch,
                                                        float* __restrict__ out) {
    char* sm = sm_raw;
    const uint32_t smem_base = smem_u32(sm);
    float* buf  = (float*)(sm + BUF_OFF);
    int*   syms = (int*)(sm + SYMS_OFF);      // [8][256]
    const uint32_t P_base = smem_base + P_OFF;
    const uint32_t E_base = smem_base + E_OFF;
    const uint32_t SMM    = smem_base + SM_M_OFF;

    const int tid  = threadIdx.x;
    const int lane = tid & 31;
    const int w    = tid >> 5;               // warp = m-tile = batch row
    const int g    = blockIdx.x >> 2;        // 0..31 batch group
    const int j    = (int)cluster_rank();    // 0..3 i-slice
    const int gb   = g * NBg + w;            // global batch row for this warp

    // ---------------- prologue ----------------
    #pragma unroll
    for (int it = 0; it < 32; it++) {
        int idx = tid + NT * it;              // 16B chunks
        int row = idx >> 6, c = idx & 63;
        *(uint4*)(sm + P_OFF + row * (ESTR * 2) + c * 16) =
            *(const uint4*)(&gPh[(j * MI + row) * NSTATES] + c * 8);
    }
    for (int idx = tid; idx < NBg * TLEN; idx += NT)
        syms[idx] = batch[(g * NBg + (idx >> 8)) * TLEN + (idx & 255)];
    __syncthreads();

    // A fragments resident in registers: warp w = m-tile w, full K=512
    uint32_t a[32][4];
    {
        const int arow  = w * 16 + (lane & 15);
        const int akoff = (lane >> 4) * 8;
        #pragma unroll
        for (int kk = 0; kk < 32; kk++) {
            uint32_t addr = P_base + (uint32_t)((arow * ESTR + kk * 16 + akoff) * 2);
            ldsm4(a[kk][0], a[kk][1], a[kk][2], a[kk][3], addr);
        }
    }
    // B ldmatrix x4 per-thread address: row = lane&7, k-block = lane>>3 (4 matrices = 32 k)
    const uint32_t b_addr4 = E_base + (uint32_t)(((lane & 7) * ESTR + (lane >> 3) * 8) * 2);

    // ---------------- step 0 (prob space) ----------------
    {
        int sy = syms[w * TLEN + 0];
        float4 et = *(const float4*)&gET[sy * NSTATES + j * MI + lane * 4];
        float4 pp = *(const float4*)&gPr[j * MI + lane * 4];
        float t0 = et.x * pp.x, t1 = et.y * pp.y, t2 = et.z * pp.z, t3 = et.w * pp.w;
        float tm = fmaxf(fmaxf(t0, t1), fmaxf(t2, t3));
        #pragma unroll
        for (int o = 16; o > 0; o >>= 1) tm = fmaxf(tm, __shfl_xor_sync(0xffffffffu, tm, o));
        float r = __fdividef(1.f, tm);
        float e0 = t0 * r, e1 = t1 * r, e2 = t2 * r, e3 = t3 * r;
        float s = e0 + e1 + e2 + e3;
        #pragma unroll
        for (int o = 16; o > 0; o >>= 1) s += __shfl_xor_sync(0xffffffffu, s, o);
        union { __half2 h[2]; uint2 uu; } cv;
        cv.h[0] = __floats2half2_rn(e0, e1);
        cv.h[1] = __floats2half2_rn(e2, e3);
        __stcg((uint2*)&gEh[0][gb][j * MI + lane * 4], cv.uu);
        if (lane == 0) {
            float mpub = __logf(tm);
            uint32_t la = SMM + (0 * 8 + w) * 16 + j * 4;
            #pragma unroll
            for (int rr = 0; rr < GI; rr++) dsmem_st_ms(la, (uint32_t)rr, mpub, s);
        }
        CLUSTER_ARRIVE();
    }

    // ---------------- main loop ----------------
    for (int t = 1; t < TLEN; ++t) {
        const int p = (t - 1) & 1, q = t & 1;
        const int outj = (t - 1) & 3;

        // prefetch before the wait (emission PROBS for this thread's 4 states)
        int sy = syms[w * TLEN + t];
        float4 et = *(const float4*)&gET[sy * NSTATES + j * MI + lane * 4];

        CLUSTER_WAIT();

        // E raw loads (L2) — 2 chunks of 16B per thread for row w
        const __half* esrc = &gEh[p][gb][0];
        uint4 er0 = __ldcg((const uint4*)(esrc + lane * 8));
        uint4 er1 = __ldcg((const uint4*)(esrc + (lane + 32) * 8));

        // per-thread stats for row w (16B LDS)
        float4 mv = *(float4*)(sm + SM_M_OFF + p * 128 + w * 16);
        float mloc = fmaxf(fmaxf(mv.x, mv.y), fmaxf(mv.z, mv.w));
        float sca = __expf(((lane >> 4) ? mv.y : mv.x) - mloc);
        float scb = __expf(((lane >> 4) ? mv.w : mv.z) - mloc);

        // rotating out-column owner
        if (j == outj && lane == 0) {
            float4 sv = *(float4*)(sm + SM_S_OFF + p * 128 + w * 16);
            float ps = __expf(mv.x - mloc) * sv.x + __expf(mv.y - mloc) * sv.y
                     + __expf(mv.z - mloc) * sv.z + __expf(mv.w - mloc) * sv.w;
            out[gb * TLEN + (t - 1)] = mloc + __logf(ps);
        }

        // stage scaled E into padded SMEM row w
        {
            char* edst = sm + E_OFF + w * (ESTR * 2);
            __half2 h2a = __half2half2(__float2half_rn(sca));
            __half2 h2b = __half2half2(__float2half_rn(scb));
            __half2* hp0 = (__half2*)&er0;
            __half2* hp1 = (__half2*)&er1;
            #pragma unroll
            for (int z = 0; z < 4; z++) { hp0[z] = __hmul2(hp0[z], h2a); hp1[z] = __hmul2(hp1[z], h2b); }
            *(uint4*)(edst + lane * 16)        = er0;
            *(uint4*)(edst + (lane + 32) * 16) = er1;
        }
        __syncthreads();

        // HMMA: m16 x n8 x K512, ldsm x4, two interleaved accumulator chains
        float aA0 = 0.f, aA1 = 0.f, aA2 = 0.f, aA3 = 0.f;
        float aB0 = 0.f, aB1 = 0.f, aB2 = 0.f, aB3 = 0.f;
        #pragma unroll
        for (int kk = 0; kk < 32; kk += 2) {
            uint32_t b0, b1, c0, c1;
            ldsm4(b0, b1, c0, c1, b_addr4 + (uint32_t)(kk * 32));
            mma16816(aA0, aA1, aA2, aA3, a[kk][0], a[kk][1], a[kk][2], a[kk][3], b0, b1);
            mma16816(aB0, aB1, aB2, aB3, a[kk+1][0], a[kk+1][1], a[kk+1][2], a[kk+1][3], c0, c1);
        }
        float f0 = aA0 + aB0, f1 = aA1 + aB1, f2 = aA2 + aB2, f3 = aA3 + aB3;

        // stash m-tile partials
        {
            float* bw = &buf[w * 162];
            int rr = lane >> 2, c = (lane & 3) * 2;
            *(float2*)&bw[rr * 10 + c]       = make_float2(f0, f1);
            *(float2*)&bw[(rr + 8) * 10 + c] = make_float2(f2, f3);
        }
        __syncthreads();

        // epilogue (prob space): t_i = C_i * em_i; normalize by warp max
        {
            int til = lane >> 2, rb = (lane & 3) * 4;
            const float* bp = &buf[til * 162 + w];
            float t0 = bp[(rb + 0) * 10] * et.x;
            float t1 = bp[(rb + 1) * 10] * et.y;
            float t2 = bp[(rb + 2) * 10] * et.z;
            float t3 = bp[(rb + 3) * 10] * et.w;
            float tm = fmaxf(fmaxf(t0, t1), fmaxf(t2, t3));
            #pragma unroll
            for (int o = 16; o > 0; o >>= 1) tm = fmaxf(tm, __shfl_xor_sync(0xffffffffu, tm, o));
            float r = __fdividef(1.f, tm);
            float e0 = t0 * r, e1 = t1 * r, e2 = t2 * r, e3 = t3 * r;
            float s = e0 + e1 + e2 + e3;
            #pragma unroll
            for (int o = 16; o > 0; o >>= 1) s += __shfl_xor_sync(0xffffffffu, s, o);
            union { __half2 h[2]; uint2 uu; } cv;
            cv.h[0] = __floats2half2_rn(e0, e1);
            cv.h[1] = __floats2half2_rn(e2, e3);
            __stcg((uint2*)&gEh[q][gb][j * MI + lane * 4], cv.uu);
            if (lane == 0) {
                float mpub = mloc + __logf(tm);
                uint32_t la = SMM + (q * 8 + w) * 16 + j * 4;
                #pragma unroll
                for (int rr = 0; rr < GI; rr++) dsmem_st_ms(la, (uint32_t)rr, mpub, s);
            }
        }

        CLUSTER_ARRIVE();
    }

    // final column t = 255 (stats buffer 1), owner j == 3
    CLUSTER_WAIT();
    if (j == 3 && tid < NBg) {
        float4 mv = *(float4*)(sm + SM_M_OFF + 128 + tid * 16);
        float4 sv = *(float4*)(sm + SM_S_OFF + 128 + tid * 16);
        float mb = fmaxf(fmaxf(mv.x, mv.y), fmaxf(mv.z, mv.w));
        float ss = __expf(mv.x - mb) * sv.x + __expf(mv.y - mb) * sv.y
                 + __expf(mv.z - mb) * sv.z + __expf(mv.w - mb) * sv.w;
        out[(g * NBg + tid) * TLEN + (TLEN - 1)] = mb + __logf(ss);
    }
}

// ---------------- launch ----------------
extern "C" void kernel_launch(void* const* d_in, const int* in_sizes, int n_in,
                              void* d_out, int out_size) {
    const int*   batch = (const int*)d_in[0];
    const float* em    = (const float*)d_in[1];
    const float* tr    = (const float*)d_in[2];
    const float* pr    = (const float*)d_in[3];
    float* out = (float*)d_out;

    cudaFuncSetAttribute(forward_kernel, cudaFuncAttributeMaxDynamicSharedMemorySize, SMEM_TOTAL);

    k_prep<<<NSTATES + 1, 256>>>(em, tr, pr);

    cudaLaunchConfig_t cfg = {};
    cfg.gridDim = dim3(NCTA, 1, 1);
    cfg.blockDim = dim3(NT, 1, 1);
    cfg.dynamicSmemBytes = SMEM_TOTAL;
    cfg.stream = 0;
    cudaLaunchAttribute attrs[1];
    attrs[0].id = cudaLaunchAttributeClusterDimension;
    attrs[0].val.clusterDim.x = GI;
    attrs[0].val.clusterDim.y = 1;
    attrs[0].val.clusterDim.z = 1;
    cfg.attrs = attrs;
    cfg.numAttrs = 1;
    cudaLaunchKernelEx(&cfg, forward_kernel, batch, out);
}

// round 13
// speedup vs baseline: 2.8993x; 1.0540x over previous
#include <cuda_runtime.h>
#include <cuda_fp16.h>
#include <cstdint>

#define NSTATES 512
#define MSYMS   256
#define BATCHN  256
#define TLEN    256

#define GB 32                // batch groups (clusters)
#define GI 4                 // cluster size (i-slices)
#define NBg 8                // batch rows per group
#define MI 128               // states per CTA
#define NCTA (GB*GI)         // 128 CTAs
#define NT 256               // 8 warps

#define ESTR 520             // fp16 row stride (1040B)

// ---- dynamic SMEM layout (bytes) ----
#define BUF_OFF    0                     // 8 tiles x 162 floats = 5184
#define SM_M_OFF   5248                  // float [2][8][4] = 256
#define SM_S_OFF   5504                  // float [2][8][4] = 256
#define P_OFF      5760                  // 128 x 520 fp16 = 133120
#define E_OFF      138880                // 8 x 520 fp16 = 8320
#define SYMS_OFF   147200                // 8 x 256 int = 8192
#define OUT_OFF    155392                // float [8][256] = 8192
#define SMEM_TOTAL 163584

// ---------------- device globals ----------------
__device__ __half gPh[NSTATES * NSTATES];   // column-softmax of transition, fp16
__device__ float  gET[MSYMS * NSTATES];     // emission PROBS transposed [sym][state]
__device__ float  gPr[NSTATES];             // prior PROBS
__device__ __half gEh[2][BATCHN][NSTATES];  // scaled E, fp16, dbl-buffered

// ---------------- PTX helpers ----------------
__device__ __forceinline__ uint32_t smem_u32(const void* p) {
    uint32_t a;
    asm("{ .reg .u64 t; cvta.to.shared.u64 t, %1; cvt.u32.u64 %0, t; }" : "=r"(a) : "l"(p));
    return a;
}
__device__ __forceinline__ uint32_t cluster_rank() {
    uint32_t r; asm("mov.u32 %0, %%cluster_ctarank;" : "=r"(r)); return r;
}
#define CLUSTER_ARRIVE() asm volatile("barrier.cluster.arrive.aligned;" ::: "memory")
#define CLUSTER_WAIT()   asm volatile("barrier.cluster.wait.aligned;"   ::: "memory")

__device__ __forceinline__ void dsmem_st_ms(uint32_t laddr_m, uint32_t rank, float mx, float sx) {
    asm volatile(
        "{\n\t.reg .b32 r;\n\t"
        "mapa.shared::cluster.u32 r, %0, %1;\n\t"
        "st.shared::cluster.f32 [r], %2;\n\t"
        "st.shared::cluster.f32 [r+256], %3;\n\t}"
        :: "r"(laddr_m), "r"(rank), "f"(mx), "f"(sx) : "memory");
}
__device__ __forceinline__ void ldsm4(uint32_t& r0, uint32_t& r1, uint32_t& r2, uint32_t& r3,
                                      uint32_t addr) {
    asm volatile("ldmatrix.sync.aligned.m8n8.x4.shared.b16 {%0,%1,%2,%3}, [%4];"
                 : "=r"(r0), "=r"(r1), "=r"(r2), "=r"(r3) : "r"(addr));
}
__device__ __forceinline__ void mma16816(float& d0, float& d1, float& d2, float& d3,
                                         uint32_t a0, uint32_t a1, uint32_t a2, uint32_t a3,
                                         uint32_t b0, uint32_t b1) {
    asm volatile(
        "mma.sync.aligned.m16n8k16.row.col.f32.f16.f16.f32 "
        "{%0,%1,%2,%3}, {%4,%5,%6,%7}, {%8,%9}, {%0,%1,%2,%3};"
        : "+f"(d0), "+f"(d1), "+f"(d2), "+f"(d3)
        : "r"(a0), "r"(a1), "r"(a2), "r"(a3), "r"(b0), "r"(b1));
}

// ---------------- fused prep kernel ----------------
__global__ void k_prep(const float* __restrict__ em, const float* __restrict__ tr,
                       const float* __restrict__ pr) {
    __shared__ float red[256];
    const int blk = blockIdx.x, t = threadIdx.x;

    if (blk < NSTATES) {
        float x = em[blk * MSYMS + t];
        red[t] = x; __syncthreads();
        for (int s = 128; s > 0; s >>= 1) { if (t < s) red[t] = fmaxf(red[t], red[t + s]); __syncthreads(); }
        float m = red[0]; __syncthreads();
        float e = __expf(x - m);
        red[t] = e; __syncthreads();
        for (int s = 128; s > 0; s >>= 1) { if (t < s) red[t] += red[t + s]; __syncthreads(); }
        gET[t * NSTATES + blk] = __fdividef(e, red[0]);   // emission prob
        __syncthreads();

        float x0 = tr[t * NSTATES + blk];
        float x1 = tr[(t + 256) * NSTATES + blk];
        red[t] = fmaxf(x0, x1); __syncthreads();
        for (int s = 128; s > 0; s >>= 1) { if (t < s) red[t] = fmaxf(red[t], red[t + s]); __syncthreads(); }
        float mm = red[0]; __syncthreads();
        red[t] = __expf(x0 - mm) + __expf(x1 - mm); __syncthreads();
        for (int s = 128; s > 0; s >>= 1) { if (t < s) red[t] += red[t + s]; __syncthreads(); }
        float clse = mm + __logf(red[0]);
        gPh[t * NSTATES + blk]         = __float2half_rn(__expf(x0 - clse));
        gPh[(t + 256) * NSTATES + blk] = __float2half_rn(__expf(x1 - clse));
    } else {
        float x0 = pr[t], x1 = pr[t + 256];
        red[t] = fmaxf(x0, x1); __syncthreads();
        for (int s = 128; s > 0; s >>= 1) { if (t < s) red[t] = fmaxf(red[t], red[t + s]); __syncthreads(); }
        float m = red[0]; __syncthreads();
        float e0 = __expf(x0 - m), e1 = __expf(x1 - m);
        red[t] = e0 + e1; __syncthreads();
        for (int s = 128; s > 0; s >>= 1) { if (t < s) red[t] += red[t + s]; __syncthreads(); }
        float inv = __fdividef(1.f, red[0]);
        gPr[t]       = e0 * inv;
        gPr[t + 256] = e1 * inv;
    }
}

// ---------------- forward kernel (4-CTA clusters) ----------------
extern __shared__ char sm_raw[];

__global__ void __launch_bounds__(NT, 1) forward_kernel(const int* __restrict__ batch,
                                                        float* __restrict__ out) {
    char* sm = sm_raw;
    const uint32_t smem_base = smem_u32(sm);
    float* buf    = (float*)(sm + BUF_OFF);
    int*   syms   = (int*)(sm + SYMS_OFF);    // [8][256]
    float* sm_out = (float*)(sm + OUT_OFF);   // [8][256]
    const uint32_t P_base = smem_base + P_OFF;
    const uint32_t E_base = smem_base + E_OFF;
    const uint32_t SMM    = smem_base + SM_M_OFF;

    const int tid  = threadIdx.x;
    const int lane = tid & 31;
    const int w    = tid >> 5;               // warp = m-tile = batch row
    const int g    = blockIdx.x >> 2;        // 0..31 batch group
    const int j    = (int)cluster_rank();    // 0..3 i-slice
    const int gb   = g * NBg + w;            // global batch row for this warp

    // ---------------- prologue ----------------
    #pragma unroll
    for (int it = 0; it < 32; it++) {
        int idx = tid + NT * it;              // 16B chunks
        int row = idx >> 6, c = idx & 63;
        *(uint4*)(sm + P_OFF + row * (ESTR * 2) + c * 16) =
            *(const uint4*)(&gPh[(j * MI + row) * NSTATES] + c * 8);
    }
    for (int idx = tid; idx < NBg * TLEN; idx += NT)
        syms[idx] = batch[(g * NBg + (idx >> 8)) * TLEN + (idx & 255)];
    __syncthreads();

    // A fragments resident in registers: warp w = m-tile w, full K=512
    uint32_t a[32][4];
    {
        const int arow  = w * 16 + (lane & 15);
        const int akoff = (lane >> 4) * 8;
        #pragma unroll
        for (int kk = 0; kk < 32; kk++) {
            uint32_t addr = P_base + (uint32_t)((arow * ESTR + kk * 16 + akoff) * 2);
            ldsm4(a[kk][0], a[kk][1], a[kk][2], a[kk][3], addr);
        }
    }
    // B ldmatrix x4 per-thread address
    const uint32_t b_addr4 = E_base + (uint32_t)(((lane & 7) * ESTR + (lane >> 3) * 8) * 2);

    // ---------------- step 0 (prob space) ----------------
    {
        int sy = syms[w * TLEN + 0];
        float4 et = *(const float4*)&gET[sy * NSTATES + j * MI + lane * 4];
        float4 pp = *(const float4*)&gPr[j * MI + lane * 4];
        float t0 = et.x * pp.x, t1 = et.y * pp.y, t2 = et.z * pp.z, t3 = et.w * pp.w;
        float tm = fmaxf(fmaxf(t0, t1), fmaxf(t2, t3));
        float sr = (t0 + t1) + (t2 + t3);
        #pragma unroll
        for (int o = 16; o > 0; o >>= 1) {
            tm = fmaxf(tm, __shfl_xor_sync(0xffffffffu, tm, o));
            sr += __shfl_xor_sync(0xffffffffu, sr, o);
        }
        float r = __fdividef(1.f, tm);
        float e0 = t0 * r, e1 = t1 * r, e2 = t2 * r, e3 = t3 * r;
        union { __half2 h[2]; uint2 uu; } cv;
        cv.h[0] = __floats2half2_rn(e0, e1);
        cv.h[1] = __floats2half2_rn(e2, e3);
        __stcg((uint2*)&gEh[0][gb][j * MI + lane * 4], cv.uu);
        if (lane == 0) {
            float mpub = __logf(tm);
            float spub = sr * r;
            uint32_t la = SMM + (0 * 8 + w) * 16 + j * 4;
            #pragma unroll
            for (int rr = 0; rr < GI; rr++) dsmem_st_ms(la, (uint32_t)rr, mpub, spub);
        }
        CLUSTER_ARRIVE();
    }

    // ---------------- main loop ----------------
    for (int t = 1; t < TLEN; ++t) {
        const int p = (t - 1) & 1, q = t & 1;

        // prefetch before the wait (emission PROBS for this thread's 4 states)
        int sy = syms[w * TLEN + t];
        float4 et = *(const float4*)&gET[sy * NSTATES + j * MI + lane * 4];

        CLUSTER_WAIT();

        // E raw loads (L2) — issue first, longest latency
        const __half* esrc = &gEh[p][gb][0];
        uint4 er0 = __ldcg((const uint4*)(esrc + lane * 8));
        uint4 er1 = __ldcg((const uint4*)(esrc + (lane + 32) * 8));

        // per-thread stats for row w (16B LDS)
        float4 mv = *(float4*)(sm + SM_M_OFF + p * 128 + w * 16);
        float mloc = fmaxf(fmaxf(mv.x, mv.y), fmaxf(mv.z, mv.w));
        float sca = __expf(((lane >> 4) ? mv.y : mv.x) - mloc);
        float scb = __expf(((lane >> 4) ? mv.w : mv.z) - mloc);

        // out column t-1 for row w: all CTAs redundantly, lane 0, into SMEM
        // (hidden in the E ldcg latency window; reuses lane0's sca/scb exps)
        if (lane == 0) {
            float4 sv = *(float4*)(sm + SM_S_OFF + p * 128 + w * 16);
            float ey = __expf(mv.y - mloc), ew = __expf(mv.w - mloc);
            float ps = sca * sv.x + ey * sv.y + scb * sv.z + ew * sv.w;
            sm_out[w * 256 + (t - 1)] = mloc + __logf(ps);
        }

        // stage scaled E into padded SMEM row w
        {
            char* edst = sm + E_OFF + w * (ESTR * 2);
            __half2 h2a = __half2half2(__float2half_rn(sca));
            __half2 h2b = __half2half2(__float2half_rn(scb));
            __half2* hp0 = (__half2*)&er0;
            __half2* hp1 = (__half2*)&er1;
            #pragma unroll
            for (int z = 0; z < 4; z++) { hp0[z] = __hmul2(hp0[z], h2a); hp1[z] = __hmul2(hp1[z], h2b); }
            *(uint4*)(edst + lane * 16)        = er0;
            *(uint4*)(edst + (lane + 32) * 16) = er1;
        }
        __syncthreads();

        // HMMA: m16 x n8 x K512, ldsm x4, two interleaved accumulator chains
        float aA0 = 0.f, aA1 = 0.f, aA2 = 0.f, aA3 = 0.f;
        float aB0 = 0.f, aB1 = 0.f, aB2 = 0.f, aB3 = 0.f;
        #pragma unroll
        for (int kk = 0; kk < 32; kk += 2) {
            uint32_t b0, b1, c0, c1;
            ldsm4(b0, b1, c0, c1, b_addr4 + (uint32_t)(kk * 32));
            mma16816(aA0, aA1, aA2, aA3, a[kk][0], a[kk][1], a[kk][2], a[kk][3], b0, b1);
            mma16816(aB0, aB1, aB2, aB3, a[kk+1][0], a[kk+1][1], a[kk+1][2], a[kk+1][3], c0, c1);
        }
        float f0 = aA0 + aB0, f1 = aA1 + aB1, f2 = aA2 + aB2, f3 = aA3 + aB3;

        // stash m-tile partials
        {
            float* bw = &buf[w * 162];
            int rr = lane >> 2, c = (lane & 3) * 2;
            *(float2*)&bw[rr * 10 + c]       = make_float2(f0, f1);
            *(float2*)&bw[(rr + 8) * 10 + c] = make_float2(f2, f3);
        }
        __syncthreads();

        // epilogue (prob space): t_i = C_i * em_i; dual interleaved reduction
        {
            int til = lane >> 2, rb = (lane & 3) * 4;
            const float* bp = &buf[til * 162 + w];
            float t0 = bp[(rb + 0) * 10] * et.x;
            float t1 = bp[(rb + 1) * 10] * et.y;
            float t2 = bp[(rb + 2) * 10] * et.z;
            float t3 = bp[(rb + 3) * 10] * et.w;
            float tm = fmaxf(fmaxf(t0, t1), fmaxf(t2, t3));
            float sr = (t0 + t1) + (t2 + t3);
            #pragma unroll
            for (int o = 16; o > 0; o >>= 1) {
                tm = fmaxf(tm, __shfl_xor_sync(0xffffffffu, tm, o));
                sr += __shfl_xor_sync(0xffffffffu, sr, o);
            }
            float r = __fdividef(1.f, tm);
            float e0 = t0 * r, e1 = t1 * r, e2 = t2 * r, e3 = t3 * r;
            union { __half2 h[2]; uint2 uu; } cv;
            cv.h[0] = __floats2half2_rn(e0, e1);
            cv.h[1] = __floats2half2_rn(e2, e3);
            __stcg((uint2*)&gEh[q][gb][j * MI + lane * 4], cv.uu);
            if (lane == 0) {
                float mpub = mloc + __logf(tm);
                float spub = sr * r;
                uint32_t la = SMM + (q * 8 + w) * 16 + j * 4;
                #pragma unroll
                for (int rr = 0; rr < GI; rr++) dsmem_st_ms(la, (uint32_t)rr, mpub, spub);
            }
        }

        CLUSTER_ARRIVE();
    }

    // final column + flush (j == 3 owns the output write)
    CLUSTER_WAIT();
    if (j == 3) {
        if (tid < NBg) {
            float4 mv = *(float4*)(sm + SM_M_OFF + 128 + tid * 16);
            float4 sv = *(float4*)(sm + SM_S_OFF + 128 + tid * 16);
            float mb = fmaxf(fmaxf(mv.x, mv.y), fmaxf(mv.z, mv.w));
            float ss = __expf(mv.x - mb) * sv.x + __expf(mv.y - mb) * sv.y
                     + __expf(mv.z - mb) * sv.z + __expf(mv.w - mb) * sv.w;
            sm_out[tid * 256 + 255] = mb + __logf(ss);
        }
        __syncthreads();
        // flush row w (coalesced float4)
        const float4* orow = (const float4*)(sm_out + w * 256);
        float4* dst = (float4*)&out[gb * TLEN];
        #pragma unroll
        for (int z = 0; z < 2; z++) dst[lane + 32 * z] = orow[lane + 32 * z];
    }
}

// ---------------- launch ----------------
extern "C" void kernel_launch(void* const* d_in, const int* in_sizes, int n_in,
                              void* d_out, int out_size) {
    const int*   batch = (const int*)d_in[0];
    const float* em    = (const float*)d_in[1];
    const float* tr    = (const float*)d_in[2];
    const float* pr    = (const float*)d_in[3];
    float* out = (float*)d_out;

    cudaFuncSetAttribute(forward_kernel, cudaFuncAttributeMaxDynamicSharedMemorySize, SMEM_TOTAL);

    k_prep<<<NSTATES + 1, 256>>>(em, tr, pr);

    cudaLaunchConfig_t cfg = {};
    cfg.gridDim = dim3(NCTA, 1, 1);
    cfg.blockDim = dim3(NT, 1, 1);
    cfg.dynamicSmemBytes = SMEM_TOTAL;
    cfg.stream = 0;
    cudaLaunchAttribute attrs[1];
    attrs[0].id = cudaLaunchAttributeClusterDimension;
    attrs[0].val.clusterDim.x = GI;
    attrs[0].val.clusterDim.y = 1;
    attrs[0].val.clusterDim.z = 1;
    cfg.attrs = attrs;
    cfg.numAttrs = 1;
    cudaLaunchKernelEx(&cfg, forward_kernel, batch, out);
}